// round 12
// baseline (speedup 1.0000x reference)
#include <cuda_runtime.h>
#include <math.h>

#define BB   2
#define SEQ  2048
#define HK   16
#define HV   32
#define DK   128
#define DV   128
#define QKV  8192
#define NTOK (BB*SEQ)
#define EPSF 1e-6f
#define TT   8          // tokens per conv block
#define NW   (NTOK/4)   // 4-token windows

// smem token layout: 8 chunks of (16 floats + 4 pad) = 160 floats per token
#define TOKSTRIDE 160

typedef unsigned long long ull;

// ---------------- packed f32x2 helpers (Blackwell) ----------------
__device__ __forceinline__ ull fma2(ull a, ull b, ull c) {
    ull d; asm("fma.rn.f32x2 %0, %1, %2, %3;" : "=l"(d) : "l"(a), "l"(b), "l"(c)); return d;
}
__device__ __forceinline__ ull mul2(ull a, ull b) {
    ull d; asm("mul.rn.f32x2 %0, %1, %2;" : "=l"(d) : "l"(a), "l"(b)); return d;
}
__device__ __forceinline__ ull pack2(float lo, float hi) {
    ull d; asm("mov.b64 %0, {%1, %2};" : "=l"(d)
               : "r"(__float_as_uint(lo)), "r"(__float_as_uint(hi))); return d;
}
__device__ __forceinline__ float hadd2(ull a) {
    unsigned lo, hi; asm("mov.b64 {%0, %1}, %2;" : "=r"(lo), "=r"(hi) : "l"(a));
    return __uint_as_float(lo) + __uint_as_float(hi);
}

// ---------------- scratch (device globals: allocation-free) ----------------
__device__ float  g_q[NTOK * HK * DK];
__device__ float  g_k[NTOK * HK * DK];
__device__ float  g_v[NTOK * HV * DV];
__device__ float2 g_gb[NTOK * HV];            // (exp(g), beta)
__device__ float  g_dt[NW * HK * 16];         // per-window pairwise dot table

// ---------------- kernel 1: causal conv + SiLU + l2norm, 8 tokens/block -----
__global__ __launch_bounds__(128) void conv_kernel(
    const float* __restrict__ x, const float* __restrict__ w)
{
    const int tile = blockIdx.x;
    const int slot = blockIdx.y;
    const int tid  = threadIdx.x;
    const int ch   = slot * 128 + tid;
    const int t0   = tile * TT;
    const int s0   = t0 & (SEQ - 1);

    const float4 wv = reinterpret_cast<const float4*>(w)[ch];

    float xv[TT + 3];
    #pragma unroll
    for (int j = 0; j < TT + 3; j++) {
        const int off = j - 3;
        xv[j] = (s0 + off >= 0) ? x[(size_t)(t0 + off) * QKV + ch] : 0.0f;
    }

    float y[TT];
    #pragma unroll
    for (int j = 0; j < TT; j++) {
        float acc = wv.x * xv[j] + wv.y * xv[j + 1] + wv.z * xv[j + 2] + wv.w * xv[j + 3];
        y[j] = acc / (1.0f + __expf(-acc));   // SiLU
    }

    if (slot < 32) {
        float ss[TT];
        #pragma unroll
        for (int j = 0; j < TT; j++) ss[j] = y[j] * y[j];
        #pragma unroll
        for (int o = 16; o; o >>= 1) {
            #pragma unroll
            for (int j = 0; j < TT; j++) ss[j] += __shfl_xor_sync(0xffffffffu, ss[j], o);
        }
        __shared__ float red[4][TT];
        if ((tid & 31) == 0) {
            #pragma unroll
            for (int j = 0; j < TT; j++) red[tid >> 5][j] = ss[j];
        }
        __syncthreads();
        #pragma unroll
        for (int j = 0; j < TT; j++) {
            float tot = red[0][j] + red[1][j] + red[2][j] + red[3][j];
            y[j] *= rsqrtf(tot + EPSF);
        }
        if (slot < 16) {
            #pragma unroll
            for (int j = 0; j < TT; j++)
                g_q[(size_t)(t0 + j) * HK * DK + slot * DK + tid] = y[j];
        } else {
            #pragma unroll
            for (int j = 0; j < TT; j++)
                g_k[(size_t)(t0 + j) * HK * DK + (slot - 16) * DK + tid] = y[j];
        }
    } else {
        #pragma unroll
        for (int j = 0; j < TT; j++)
            g_v[(size_t)(t0 + j) * HV * DV + (slot - 32) * DV + tid] = y[j];
    }
}

// ---------------- kernel 2: gating precompute --------------------------------
__global__ void gate_kernel(const float* __restrict__ b_in,
                            const float* __restrict__ a_in,
                            const float* __restrict__ dt_bias,
                            const float* __restrict__ alog)
{
    int i = blockIdx.x * blockDim.x + threadIdx.x;
    if (i >= NTOK * HV) return;
    int h = i & (HV - 1);
    float xx = a_in[i] + dt_bias[h];
    float sp = fmaxf(xx, 0.0f) + log1pf(expf(-fabsf(xx)));
    float g  = -expf(alog[h]) * sp;
    float eg = expf(g);
    float bb = b_in[i];
    float beta = 1.0f / (1.0f + expf(-bb));
    g_gb[i] = make_float2(eg, beta);
}

// ---------------- kernel 2.5: per-window pairwise dot table ------------------
__device__ __forceinline__ float dot4(float4 a, float4 b) {
    return a.x*b.x + a.y*b.y + a.z*b.z + a.w*b.w;
}
__global__ __launch_bounds__(128) void dot_kernel()
{
    const int warp = threadIdx.x >> 5;
    const int lane = threadIdx.x & 31;
    const int w    = blockIdx.x * 4 + warp;
    const int hk   = blockIdx.y;

    const size_t base = (size_t)(w * 4) * (HK * DK) + hk * DK + lane * 4;
    float4 k[4], q[4];
    #pragma unroll
    for (int i = 0; i < 4; i++) {
        k[i] = *reinterpret_cast<const float4*>(&g_k[base + (size_t)i * (HK * DK)]);
        q[i] = *reinterpret_cast<const float4*>(&g_q[base + (size_t)i * (HK * DK)]);
    }
    float s0  = dot4(k[1], k[0]), s1  = dot4(k[2], k[0]), s2  = dot4(k[2], k[1]);
    float s3  = dot4(k[3], k[0]), s4  = dot4(k[3], k[1]), s5  = dot4(k[3], k[2]);
    float s6  = dot4(q[0], k[0]), s7  = dot4(q[1], k[0]), s8  = dot4(q[1], k[1]);
    float s9  = dot4(q[2], k[0]), s10 = dot4(q[2], k[1]), s11 = dot4(q[2], k[2]);
    float s12 = dot4(q[3], k[0]), s13 = dot4(q[3], k[1]), s14 = dot4(q[3], k[2]);
    float s15 = dot4(q[3], k[3]);
    #pragma unroll
    for (int o = 16; o; o >>= 1) {
        s0  += __shfl_xor_sync(~0u, s0,  o); s1  += __shfl_xor_sync(~0u, s1,  o);
        s2  += __shfl_xor_sync(~0u, s2,  o); s3  += __shfl_xor_sync(~0u, s3,  o);
        s4  += __shfl_xor_sync(~0u, s4,  o); s5  += __shfl_xor_sync(~0u, s5,  o);
        s6  += __shfl_xor_sync(~0u, s6,  o); s7  += __shfl_xor_sync(~0u, s7,  o);
        s8  += __shfl_xor_sync(~0u, s8,  o); s9  += __shfl_xor_sync(~0u, s9,  o);
        s10 += __shfl_xor_sync(~0u, s10, o); s11 += __shfl_xor_sync(~0u, s11, o);
        s12 += __shfl_xor_sync(~0u, s12, o); s13 += __shfl_xor_sync(~0u, s13, o);
        s14 += __shfl_xor_sync(~0u, s14, o); s15 += __shfl_xor_sync(~0u, s15, o);
    }
    if (lane == 0) {
        float4* p = reinterpret_cast<float4*>(&g_dt[(size_t)(w * HK + hk) * 16]);
        p[0] = make_float4(s0,  s1,  s2,  s3);
        p[1] = make_float4(s4,  s5,  s6,  s7);
        p[2] = make_float4(s8,  s9,  s10, s11);
        p[3] = make_float4(s12, s13, s14, s15);
    }
}

// ---------------- kernel 3: windowed gated delta-rule scan (f32x2 core) ------
// grid: 256 (= B*HV * 4 column-quarters), block: 128 (4 warps), 2 blocks/SM.
// Two independent blocks co-resident per SM give each SMSP two warps from
// INDEPENDENT barriers, hiding the per-window serial chain (shfl reductions +
// scalar recurrence) of one block under the FMA work of the other.
// Thread owns 16 rows x 2 cols; state packed as 8 row-pairs x 2 cols of f32x2.
__global__ __launch_bounds__(128, 2) void scan_kernel(float* __restrict__ out)
{
    const int blk  = blockIdx.x;
    const int bh   = blk >> 2;
    const int quar = blk & 3;
    const int bb   = bh / HV;
    const int h    = bh % HV;
    const int hk   = h >> 1;              // GQA
    const int tid  = threadIdx.x;
    const int lane = tid & 31;
    const int warp = tid >> 5;                    // 0..3
    const int rp   = lane >> 2;                   // 0..7 row partition (16 rows)
    const int cg   = warp * 4 + (lane & 3);       // 0..15 col pair
    const int col0 = quar * 32 + cg * 2;
    const float scale = 0.08838834764831845f;     // 128^-0.5

    __shared__ __align__(16) float ksh[2][4 * TOKSTRIDE];
    __shared__ __align__(16) float qsh[2][4 * TOKSTRIDE];

    // S2[rr*2 + c] = f32x2 over rows (2rr, 2rr+1) of column c, rr = 0..7
    ull S2[16];
    #pragma unroll
    for (int i = 0; i < 16; i++) S2[i] = 0ull;

    const size_t row0 = (size_t)bb * SEQ;

    // staging role: thread stages 4 consecutive floats of one token's k and q
    const int ptok  = warp;                       // 0..3 (token of the window)
    const int ppos  = lane * 4;                   // 0..124
    const int psmem = ptok * TOKSTRIDE + (ppos >> 4) * 20 + (ppos & 15);

    // ---- prefetch window 0 ----
    float4 kv = *reinterpret_cast<const float4*>(
        &g_k[(row0 + ptok) * (HK * DK) + hk * DK + ppos]);
    float4 qv = *reinterpret_cast<const float4*>(
        &g_q[(row0 + ptok) * (HK * DK) + hk * DK + ppos]);
    float2 vp[4]; float2 gbp[4];
    #pragma unroll
    for (int i = 0; i < 4; i++) {
        vp[i]  = *reinterpret_cast<const float2*>(
            &g_v[(row0 + i) * (HV * DV) + h * DV + col0]);
        gbp[i] = g_gb[(row0 + i) * HV + h];
    }
    size_t dtb = ((row0 >> 2) * HK + hk) * 4;     // float4 index into g_dt
    const float4* dtp = reinterpret_cast<const float4*>(g_dt);
    float4 T0 = dtp[dtb], T1 = dtp[dtb + 1], T2 = dtp[dtb + 2], T3 = dtp[dtb + 3];

    for (int w = 0; w < SEQ / 4; w++) {
        const int pb = w & 1;
        *reinterpret_cast<float4*>(&ksh[pb][psmem]) = kv;
        *reinterpret_cast<float4*>(&qsh[pb][psmem]) = qv;
        const float2 v0 = vp[0], v1 = vp[1], v2 = vp[2], v3 = vp[3];
        const float d0 = gbp[0].x, d1 = gbp[1].x, d2 = gbp[2].x, d3 = gbp[3].x;
        const float b0 = gbp[0].y, b1 = gbp[1].y, b2 = gbp[2].y, b3 = gbp[3].y;
        const float4 A0 = T0, A1 = T1, A2 = T2, A3 = T3;
        __syncthreads();

        // ---- prefetch window w+1 ----
        if (w + 1 < SEQ / 4) {
            const size_t tn = row0 + (size_t)(w + 1) * 4;
            kv = *reinterpret_cast<const float4*>(
                &g_k[(tn + ptok) * (HK * DK) + hk * DK + ppos]);
            qv = *reinterpret_cast<const float4*>(
                &g_q[(tn + ptok) * (HK * DK) + hk * DK + ppos]);
            #pragma unroll
            for (int i = 0; i < 4; i++) {
                vp[i]  = *reinterpret_cast<const float2*>(
                    &g_v[(tn + i) * (HV * DV) + h * DV + col0]);
                gbp[i] = g_gb[(tn + i) * HV + h];
            }
            dtb += HK * 4;
            T0 = dtp[dtb]; T1 = dtp[dtb + 1]; T2 = dtp[dtb + 2]; T3 = dtp[dtb + 3];
        }

        const float* kb = &ksh[pb][rp * 20];      // my 16-row chunk
        const float* qb = &qsh[pb][rp * 20];

        // ---- packed dot pass: kp2[i*2+c] accumulates k_i(row-pairs).S0[:,c]
        ull kp2[8], qp2[8];
        #pragma unroll
        for (int i = 0; i < 8; i++) { kp2[i] = 0ull; qp2[i] = 0ull; }
        #pragma unroll
        for (int i = 0; i < 4; i++) {
            const ulonglong2* kt = reinterpret_cast<const ulonglong2*>(kb + i * TOKSTRIDE);
            const ulonglong2* qt = reinterpret_cast<const ulonglong2*>(qb + i * TOKSTRIDE);
            #pragma unroll
            for (int r = 0; r < 4; r++) {
                const ulonglong2 kk = kt[r];      // .x = rows(4r,4r+1), .y = rows(4r+2,4r+3)
                const ulonglong2 qq = qt[r];
                kp2[i*2+0] = fma2(kk.x, S2[(2*r  )*2+0], kp2[i*2+0]);
                kp2[i*2+1] = fma2(kk.x, S2[(2*r  )*2+1], kp2[i*2+1]);
                kp2[i*2+0] = fma2(kk.y, S2[(2*r+1)*2+0], kp2[i*2+0]);
                kp2[i*2+1] = fma2(kk.y, S2[(2*r+1)*2+1], kp2[i*2+1]);
                qp2[i*2+0] = fma2(qq.x, S2[(2*r  )*2+0], qp2[i*2+0]);
                qp2[i*2+1] = fma2(qq.x, S2[(2*r  )*2+1], qp2[i*2+1]);
                qp2[i*2+0] = fma2(qq.y, S2[(2*r+1)*2+0], qp2[i*2+0]);
                qp2[i*2+1] = fma2(qq.y, S2[(2*r+1)*2+1], qp2[i*2+1]);
            }
        }
        float kp[8], qp[8];
        #pragma unroll
        for (int i = 0; i < 8; i++) { kp[i] = hadd2(kp2[i]); qp[i] = hadd2(qp2[i]); }
        // reduce across the 8 row partitions (lane bits 2,3,4)
        #pragma unroll
        for (int i = 0; i < 8; i++) {
            kp[i] += __shfl_xor_sync(~0u, kp[i], 4);
            kp[i] += __shfl_xor_sync(~0u, kp[i], 8);
            kp[i] += __shfl_xor_sync(~0u, kp[i], 16);
            qp[i] += __shfl_xor_sync(~0u, qp[i], 4);
            qp[i] += __shfl_xor_sync(~0u, qp[i], 8);
            qp[i] += __shfl_xor_sync(~0u, qp[i], 16);
        }

        // ---- scalar window recurrence, per column ----
        const float D1 = d0, D2 = D1 * d1, D3 = D2 * d2, D4 = D3 * d3;
        const float f12 = d1, f23 = d2, f34 = d3;
        const float f13 = d1 * d2, f24 = d2 * d3;
        const float f14 = f13 * d3;
        float u1[2], u2[2], u3[2], u4[2], o1[2], o2[2], o3[2], o4[2];
        float e1[2], e2[2], e3[2], e4[2];
        const float vv0[2] = {v0.x, v0.y}, vv1[2] = {v1.x, v1.y};
        const float vv2[2] = {v2.x, v2.y}, vv3[2] = {v3.x, v3.y};
        #pragma unroll
        for (int c = 0; c < 2; c++) {
            u1[c] = b0 * (vv0[c] - d0 * kp[0*2+c]);
            u2[c] = b1 * (vv1[c] - d1 * (D1 * kp[1*2+c] + A0.x * u1[c]));
            u3[c] = b2 * (vv2[c] - d2 * (D2 * kp[2*2+c] + f12 * A0.y * u1[c] + A0.z * u2[c]));
            u4[c] = b3 * (vv3[c] - d3 * (D3 * kp[3*2+c] + f13 * A0.w * u1[c]
                                         + f23 * A1.x * u2[c] + A1.y * u3[c]));
            o1[c] = (D1 * qp[0*2+c] + A1.z * u1[c]) * scale;
            o2[c] = (D2 * qp[1*2+c] + f12 * A1.w * u1[c] + A2.x * u2[c]) * scale;
            o3[c] = (D3 * qp[2*2+c] + f13 * A2.y * u1[c] + f23 * A2.z * u2[c]
                     + A2.w * u3[c]) * scale;
            o4[c] = (D4 * qp[3*2+c] + f14 * A3.x * u1[c] + f24 * A3.y * u2[c]
                     + f34 * A3.z * u3[c] + A3.w * u4[c]) * scale;
            e1[c] = f14 * u1[c]; e2[c] = f24 * u2[c]; e3[c] = f34 * u3[c]; e4[c] = u4[c];
        }

        // ---- packed rank-4 update: S = D4*S + sum_j k_j * e_j ----
        const ull D4_2 = pack2(D4, D4);
        ull e1_2[2], e2_2[2], e3_2[2], e4_2[2];
        #pragma unroll
        for (int c = 0; c < 2; c++) {
            e1_2[c] = pack2(e1[c], e1[c]); e2_2[c] = pack2(e2[c], e2[c]);
            e3_2[c] = pack2(e3[c], e3[c]); e4_2[c] = pack2(e4[c], e4[c]);
        }
        {
            const ulonglong2* t1 = reinterpret_cast<const ulonglong2*>(kb + 0 * TOKSTRIDE);
            const ulonglong2* t2 = reinterpret_cast<const ulonglong2*>(kb + 1 * TOKSTRIDE);
            const ulonglong2* t3 = reinterpret_cast<const ulonglong2*>(kb + 2 * TOKSTRIDE);
            const ulonglong2* t4 = reinterpret_cast<const ulonglong2*>(kb + 3 * TOKSTRIDE);
            #pragma unroll
            for (int r = 0; r < 4; r++) {
                const ulonglong2 k1 = t1[r], k2 = t2[r], k3 = t3[r], k4 = t4[r];
                #pragma unroll
                for (int c = 0; c < 2; c++) {
                    ull a0 = mul2(k1.x, e1_2[c]);
                    a0 = fma2(k2.x, e2_2[c], a0);
                    a0 = fma2(k3.x, e3_2[c], a0);
                    a0 = fma2(k4.x, e4_2[c], a0);
                    S2[(2*r  )*2+c] = fma2(S2[(2*r  )*2+c], D4_2, a0);
                    ull a1 = mul2(k1.y, e1_2[c]);
                    a1 = fma2(k2.y, e2_2[c], a1);
                    a1 = fma2(k3.y, e3_2[c], a1);
                    a1 = fma2(k4.y, e4_2[c], a1);
                    S2[(2*r+1)*2+c] = fma2(S2[(2*r+1)*2+c], D4_2, a1);
                }
            }
        }

        // ---- output: rp 0..3 writes token w*4+rp, both cols (float2) ----
        if (rp < 4) {
            const float ox = (rp == 0) ? o1[0] : (rp == 1) ? o2[0] : (rp == 2) ? o3[0] : o4[0];
            const float oy = (rp == 0) ? o1[1] : (rp == 1) ? o2[1] : (rp == 2) ? o3[1] : o4[1];
            *reinterpret_cast<float2*>(
                &out[((row0 + (size_t)w * 4 + rp) * HV + h) * DV + col0]) = make_float2(ox, oy);
        }
    }
}

// ---------------- launch ------------------------------------------------------
extern "C" void kernel_launch(void* const* d_in, const int* in_sizes, int n_in,
                              void* d_out, int out_size)
{
    const float* x    = (const float*)d_in[0];  // mixed_qkv [4096, 8192]
    const float* b    = (const float*)d_in[1];  // [4096, 32]
    const float* a    = (const float*)d_in[2];  // [4096, 32]
    const float* w    = (const float*)d_in[3];  // conv_weights [8192, 4]
    const float* dt   = (const float*)d_in[4];  // [32]
    const float* alog = (const float*)d_in[5];  // [32]
    // d_in[6] = cu_seqlens (equal-length; unused)

    conv_kernel<<<dim3(NTOK / TT, 64), 128>>>(x, w);
    gate_kernel<<<(NTOK * HV + 255) / 256, 256>>>(b, a, dt, alog);
    dot_kernel<<<dim3(NW / 4, HK), 128>>>();
    scan_kernel<<<256, 128>>>((float*)d_out);
}